// round 1
// baseline (speedup 1.0000x reference)
#include <cuda_runtime.h>
#include <math.h>

#define Tt   64
#define Bb   128
#define Ee   1024
#define Hh   1024
#define Vv   10000
#define NBLK 12
#define GRID_R 128

// ---------------- scratch (device globals; no allocation allowed) ----------------
__device__ float g_XC[Tt*Bb*Hh];     // x @ wxc^T + b   (T*B, H)
__device__ float g_XH[Tt*Bb*Hh];     // x @ wxh^T + b
__device__ float g_OUT[Tt*Bb*Hh];    // pre-clip hidden per step (decoder input)
__device__ float g_H[Bb*Hh];         // carried hidden
__device__ float g_Pc[8*Bb*Hh];      // split-K partials, gate path
__device__ float g_Ph[8*Bb*Hh];      // split-K partials, cand path
__device__ unsigned g_count = 0;
__device__ volatile unsigned g_epoch = 0;

// ---------------- helpers ----------------
__device__ __forceinline__ unsigned f2tf32(float x){
  unsigned u;
  asm("cvt.rna.tf32.f32 %0, %1;" : "=r"(u) : "f"(x));
  return u;
}

__device__ __forceinline__ void mma_tf32(float* c, const unsigned* a, const unsigned* b){
  asm volatile(
    "mma.sync.aligned.m16n8k8.row.col.f32.tf32.tf32.f32 "
    "{%0,%1,%2,%3}, {%4,%5,%6,%7}, {%8,%9}, {%0,%1,%2,%3};\n"
    : "+f"(c[0]), "+f"(c[1]), "+f"(c[2]), "+f"(c[3])
    : "r"(a[0]), "r"(a[1]), "r"(a[2]), "r"(a[3]), "r"(b[0]), "r"(b[1]));
}

// CTA tile 128x128, 8 warps as 2(M)x4(N) warp tiles of 64x32, KBLK=32.
__device__ __forceinline__ void compute_kblk(const unsigned (*As)[36], const unsigned (*Bs)[36],
                                             float acc[4][4][4], int wm, int wn, int g, int tg){
#pragma unroll
  for (int ks = 0; ks < 32; ks += 8){
    unsigned a[4][4], b[4][2];
#pragma unroll
    for (int mi = 0; mi < 4; mi++){
      int r = wm + mi*16 + g;
      a[mi][0] = As[r][ks+tg];
      a[mi][1] = As[r+8][ks+tg];
      a[mi][2] = As[r][ks+tg+4];
      a[mi][3] = As[r+8][ks+tg+4];
    }
#pragma unroll
    for (int ni = 0; ni < 4; ni++){
      int rr = wn + ni*8 + g;
      b[ni][0] = Bs[rr][ks+tg];
      b[ni][1] = Bs[rr][ks+tg+4];
    }
#pragma unroll
    for (int mi = 0; mi < 4; mi++)
#pragma unroll
      for (int ni = 0; ni < 4; ni++)
        mma_tf32(acc[mi][ni], a[mi], b[ni]);
  }
}

__device__ __forceinline__ float sigm(float x){ return 1.f/(1.f + expf(-x)); }

// grid-wide barrier; requires all CTAs co-resident (grid=128 <= #SMs, 1 CTA/SM)
__device__ __forceinline__ void gsync(){
  __syncthreads();
  if (threadIdx.x == 0){
    unsigned e = g_epoch;
    __threadfence();
    if (atomicAdd(&g_count, 1) == gridDim.x - 1){
      g_count = 0;
      __threadfence();
      g_epoch = e + 1;
    } else {
      while (g_epoch == e) { }
    }
    __threadfence();
  }
  __syncthreads();
}

// ---------------- phase 1: embedding gather + input projections ----------------
__global__ void __launch_bounds__(256) xproj_kernel(
    const int* __restrict__ tokens, const float* __restrict__ embW,
    const float* __restrict__ wxcW, const float* __restrict__ wxcB,
    const float* __restrict__ wxhW, const float* __restrict__ wxhB)
{
  __shared__ unsigned As[128][36];
  __shared__ unsigned Bs[128][36];
  __shared__ int toks[128];
  const int tid = threadIdx.x;
  const int n0 = blockIdx.x * 128;
  const int m0 = blockIdx.y * 128;
  const int mat = blockIdx.z;
  const float* W    = mat ? wxhW : wxcW;
  const float* bias = mat ? wxhB : wxcB;
  float* Cout = mat ? g_XH : g_XC;
  if (tid < 128) toks[tid] = tokens[m0 + tid];
  const int lane = tid & 31, warp = tid >> 5;
  const int wm = (warp & 1) * 64, wn = (warp >> 1) * 32;
  const int g = lane >> 2, tg = lane & 3;
  float acc[4][4][4];
#pragma unroll
  for (int a=0;a<4;a++)
#pragma unroll
    for (int b=0;b<4;b++)
#pragma unroll
      for (int c=0;c<4;c++) acc[a][b][c]=0.f;

  for (int kb = 0; kb < Ee; kb += 32){
    __syncthreads();
#pragma unroll
    for (int i = 0; i < 4; i++){
      int idx = tid + i*256;
      int row = idx >> 3;
      int cc  = (idx & 7) * 4;
      float4 v = *(const float4*)(embW + (size_t)toks[row]*Ee + kb + cc);
      As[row][cc+0]=f2tf32(v.x); As[row][cc+1]=f2tf32(v.y);
      As[row][cc+2]=f2tf32(v.z); As[row][cc+3]=f2tf32(v.w);
      float4 u = *(const float4*)(W + (size_t)(n0+row)*Ee + kb + cc);
      Bs[row][cc+0]=f2tf32(u.x); Bs[row][cc+1]=f2tf32(u.y);
      Bs[row][cc+2]=f2tf32(u.z); Bs[row][cc+3]=f2tf32(u.w);
    }
    __syncthreads();
    compute_kblk(As, Bs, acc, wm, wn, g, tg);
  }
#pragma unroll
  for (int mi=0; mi<4; mi++){
    int r = m0 + wm + mi*16 + g;
#pragma unroll
    for (int ni=0; ni<4; ni++){
      int c = n0 + wn + ni*8 + 2*tg;
      float b0 = bias[c], b1 = bias[c+1];
      size_t o = (size_t)r*Hh + c;
      Cout[o]        = acc[mi][ni][0] + b0;
      Cout[o+1]      = acc[mi][ni][1] + b1;
      Cout[o+8*Hh]   = acc[mi][ni][2] + b0;
      Cout[o+8*Hh+1] = acc[mi][ni][3] + b1;
    }
  }
}

// ---------------- phase 2: persistent recurrence kernel ----------------
// 128 CTAs: bid = kc(3b) | nt(3b) | mat(1b). Each stage: per-CTA 128x128x128
// partial GEMM -> barrier -> fused reduce+gate+activation -> barrier.
__global__ void __launch_bounds__(256) rnn_kernel(
  const float* __restrict__ w_hc, const float* __restrict__ w_hh,
  const float* __restrict__ edge_h, const float* __restrict__ edge_c,
  float* __restrict__ outp)
{
  __shared__ unsigned As[128][36];
  __shared__ unsigned Bs[128][36];
  __shared__ float red[9];
  const int tid = threadIdx.x;
  const int bid = blockIdx.x;
  const int lane = tid & 31, warp = tid >> 5;
  const int wm = (warp & 1) * 64, wn = (warp >> 1) * 32;
  const int g = lane >> 2, tg = lane & 3;
  const int kc  = bid & 7;
  const int nt  = (bid >> 3) & 7;
  const int mat = bid >> 6;
  const int n0 = nt * 128;
  const int k0 = kc * 128;
  const int f  = bid * 256 + tid;   // global float4 index, [0, 32768)

  // h0 = 0 (must re-init every call: deterministic)
  for (int i = f; i < Bb*Hh; i += GRID_R*256) g_H[i] = 0.f;
  gsync();

  for (int t = 0; t < Tt; t++){
    for (int s = 0; s < NBLK; s++){
      const float* W;
      if (s == 0) W = mat ? w_hh : w_hc;
      else        W = (mat ? edge_h : edge_c) + (size_t)(s-1)*Hh*Hh;

      float acc[4][4][4];
#pragma unroll
      for (int a=0;a<4;a++)
#pragma unroll
        for (int b2=0;b2<4;b2++)
#pragma unroll
          for (int c=0;c<4;c++) acc[a][b2][c]=0.f;

      for (int kb = 0; kb < 128; kb += 32){
        __syncthreads();
#pragma unroll
        for (int i = 0; i < 4; i++){
          int idx = tid + i*256;
          int row = idx >> 3;
          int cc  = (idx & 7) * 4;
          float4 v = *(const float4*)(g_H + (size_t)row*Hh + k0 + kb + cc);
          As[row][cc+0]=f2tf32(v.x); As[row][cc+1]=f2tf32(v.y);
          As[row][cc+2]=f2tf32(v.z); As[row][cc+3]=f2tf32(v.w);
          float4 u = *(const float4*)(W + (size_t)(n0+row)*Hh + k0 + kb + cc);
          Bs[row][cc+0]=f2tf32(u.x); Bs[row][cc+1]=f2tf32(u.y);
          Bs[row][cc+2]=f2tf32(u.z); Bs[row][cc+3]=f2tf32(u.w);
        }
        __syncthreads();
        compute_kblk(As, Bs, acc, wm, wn, g, tg);
      }
      // write split-K partial
      float* Pd = (mat ? g_Ph : g_Pc) + ((size_t)kc << 17);
#pragma unroll
      for (int mi=0; mi<4; mi++){
        int r = wm + mi*16 + g;
#pragma unroll
        for (int ni=0; ni<4; ni++){
          int c = n0 + wn + ni*8 + 2*tg;
          Pd[(size_t)r*Hh + c]       = acc[mi][ni][0];
          Pd[(size_t)r*Hh + c+1]     = acc[mi][ni][1];
          Pd[(size_t)(r+8)*Hh + c]   = acc[mi][ni][2];
          Pd[(size_t)(r+8)*Hh + c+1] = acc[mi][ni][3];
        }
      }
      gsync();

      // fused reduce + gate + activation + blend (one float4 per thread)
      {
        float4 sc = make_float4(0.f,0.f,0.f,0.f);
        float4 sh = make_float4(0.f,0.f,0.f,0.f);
#pragma unroll
        for (int k = 0; k < 8; k++){
          float4 a  = *(const float4*)(g_Pc + ((size_t)k<<17) + ((size_t)f<<2));
          sc.x += a.x; sc.y += a.y; sc.z += a.z; sc.w += a.w;
          float4 b2 = *(const float4*)(g_Ph + ((size_t)k<<17) + ((size_t)f<<2));
          sh.x += b2.x; sh.y += b2.y; sh.z += b2.z; sh.w += b2.w;
        }
        if (s == 0){
          float4 a  = *(const float4*)(g_XC + ((size_t)t<<17) + ((size_t)f<<2));
          sc.x += a.x; sc.y += a.y; sc.z += a.z; sc.w += a.w;
          float4 b2 = *(const float4*)(g_XH + ((size_t)t<<17) + ((size_t)f<<2));
          sh.x += b2.x; sh.y += b2.y; sh.z += b2.z; sh.w += b2.w;
        }
        float4 h = *(const float4*)(g_H + ((size_t)f<<2));
        const bool use_tanh = (s == 0) || (s & 1);   // F0=tanh; edges alternate tanh/relu
        float gx = sigm(sc.x), gy = sigm(sc.y), gz = sigm(sc.z), gw = sigm(sc.w);
        float ax = use_tanh ? tanhf(sh.x) : fmaxf(sh.x, 0.f);
        float ay = use_tanh ? tanhf(sh.y) : fmaxf(sh.y, 0.f);
        float az = use_tanh ? tanhf(sh.z) : fmaxf(sh.z, 0.f);
        float aw = use_tanh ? tanhf(sh.w) : fmaxf(sh.w, 0.f);
        float4 hn;
        hn.x = gx*ax + (1.f-gx)*h.x;
        hn.y = gy*ay + (1.f-gy)*h.y;
        hn.z = gz*az + (1.f-gz)*h.z;
        hn.w = gw*aw + (1.f-gw)*h.w;
        *(float4*)(g_H + ((size_t)f<<2)) = hn;
        if (s == NBLK-1)
          *(float4*)(g_OUT + ((size_t)t<<17) + ((size_t)f<<2)) = hn;   // pre-clip output
      }
      gsync();
    }

    // per-row hidden-norm clip (CTA b owns row b); carried h only
    {
      float* hr = g_H + (size_t)bid * Hh;
      float ss = 0.f;
      for (int i = tid; i < Hh; i += 256){ float v = hr[i]; ss += v*v; }
#pragma unroll
      for (int off = 16; off > 0; off >>= 1) ss += __shfl_xor_sync(0xffffffffu, ss, off);
      if (lane == 0) red[warp] = ss;
      __syncthreads();
      if (tid == 0){
        float tot = 0.f;
        for (int w2 = 0; w2 < 8; w2++) tot += red[w2];
        float nrm = sqrtf(tot);
        red[8] = (nrm > 25.f) ? (25.f / nrm) : 1.f;
      }
      __syncthreads();
      float scale = red[8];
      if (scale != 1.f)
        for (int i = tid; i < Hh; i += 256) hr[i] *= scale;
    }
    gsync();
  }

  // hT (clipped final hidden) appended after decoded
  for (int i = f; i < Bb*Hh; i += GRID_R*256)
    outp[(size_t)Tt*Bb*Vv + i] = g_H[i];
}

// ---------------- phase 3: decoder GEMM (8192x1024 @ 1024x10000 + bias) ----------------
__global__ void __launch_bounds__(256) dec_kernel(
  const float* __restrict__ decW, const float* __restrict__ decB, float* __restrict__ outp)
{
  __shared__ unsigned As[128][36];
  __shared__ unsigned Bs[128][36];
  const int tid = threadIdx.x;
  const int n0 = blockIdx.x * 128;
  const int m0 = blockIdx.y * 128;
  const int lane = tid & 31, warp = tid >> 5;
  const int wm = (warp & 1) * 64, wn = (warp >> 1) * 32;
  const int g = lane >> 2, tg = lane & 3;
  float acc[4][4][4];
#pragma unroll
  for (int a=0;a<4;a++)
#pragma unroll
    for (int b=0;b<4;b++)
#pragma unroll
      for (int c=0;c<4;c++) acc[a][b][c]=0.f;

  for (int kb = 0; kb < Hh; kb += 32){
    __syncthreads();
#pragma unroll
    for (int i = 0; i < 4; i++){
      int idx = tid + i*256;
      int row = idx >> 3;
      int cc  = (idx & 7) * 4;
      float4 v = *(const float4*)(g_OUT + (size_t)(m0+row)*Hh + kb + cc);
      As[row][cc+0]=f2tf32(v.x); As[row][cc+1]=f2tf32(v.y);
      As[row][cc+2]=f2tf32(v.z); As[row][cc+3]=f2tf32(v.w);
      int brow = n0 + row;
      float4 u = make_float4(0.f,0.f,0.f,0.f);
      if (brow < Vv) u = *(const float4*)(decW + (size_t)brow*Hh + kb + cc);
      Bs[row][cc+0]=f2tf32(u.x); Bs[row][cc+1]=f2tf32(u.y);
      Bs[row][cc+2]=f2tf32(u.z); Bs[row][cc+3]=f2tf32(u.w);
    }
    __syncthreads();
    compute_kblk(As, Bs, acc, wm, wn, g, tg);
  }
#pragma unroll
  for (int mi=0;mi<4;mi++){
    int r = m0 + wm + mi*16 + g;
#pragma unroll
    for (int ni=0;ni<4;ni++){
      int c = n0 + wn + ni*8 + 2*tg;
      if (c < Vv){   // c is even, Vv even -> c+1 also in range
        float b0 = decB[c], b1 = decB[c+1];
        size_t o  = (size_t)r*Vv + c;
        size_t o2 = o + (size_t)8*Vv;
        outp[o]    = acc[mi][ni][0] + b0;
        outp[o+1]  = acc[mi][ni][1] + b1;
        outp[o2]   = acc[mi][ni][2] + b0;
        outp[o2+1] = acc[mi][ni][3] + b1;
      }
    }
  }
}

// ---------------- launch ----------------
extern "C" void kernel_launch(void* const* d_in, const int* in_sizes, int n_in,
                              void* d_out, int out_size){
  const int*   tokens = (const int*)  d_in[0];
  const float* embW   = (const float*)d_in[1];
  const float* wxcW   = (const float*)d_in[2];
  const float* wxcB   = (const float*)d_in[3];
  const float* wxhW   = (const float*)d_in[4];
  const float* wxhB   = (const float*)d_in[5];
  const float* w_hc   = (const float*)d_in[6];
  const float* w_hh   = (const float*)d_in[7];
  const float* edge_h = (const float*)d_in[8];
  const float* edge_c = (const float*)d_in[9];
  const float* decW   = (const float*)d_in[10];
  const float* decB   = (const float*)d_in[11];
  float* outp = (float*)d_out;
  (void)in_sizes; (void)n_in; (void)out_size;

  xproj_kernel<<<dim3(8, 64, 2), 256>>>(tokens, embW, wxcW, wxcB, wxhW, wxhB);
  rnn_kernel<<<GRID_R, 256>>>(w_hc, w_hh, edge_h, edge_c, outp);
  dec_kernel<<<dim3((Vv + 127) / 128, 64), 256>>>(decW, decB, outp);
}

// round 2
// speedup vs baseline: 1.2488x; 1.2488x over previous
#include <cuda_runtime.h>
#include <math.h>

#define Tt   64
#define Bb   128
#define Ee   1024
#define Hh   1024
#define Vv   10000
#define NBLK 12
#define GRID_R 128
#define VPAD 10112
#define PIPE 3

// ---------------- scratch (device globals; no allocation allowed) ----------------
__device__ __align__(16) float g_XC[Tt*Bb*Hh];     // x @ wxc^T + b (f32)
__device__ __align__(16) float g_XH[Tt*Bb*Hh];     // x @ wxh^T + b (f32)
__device__ __align__(16) float g_OUT[Tt*Bb*Hh];    // tf32-rounded pre-clip hidden (decoder A)
__device__ __align__(16) float g_H[Bb*Hh];         // carried hidden f32
__device__ __align__(16) float g_Htf[Bb*Hh];       // tf32-rounded twin (GEMM A)
__device__ __align__(16) float g_Pc[4*Bb*Hh];      // split-K partials, gate path
__device__ __align__(16) float g_Ph[4*Bb*Hh];      // split-K partials, cand path
__device__ __align__(16) float g_Wc[NBLK*Hh*Hh];   // rounded [w_hc, edge_c x11]
__device__ __align__(16) float g_Wh[NBLK*Hh*Hh];   // rounded [w_hh, edge_h x11]
__device__ __align__(16) float g_We[Vv*Ee];        // rounded embedding
__device__ __align__(16) float g_Wx[2*Hh*Ee];      // rounded wxc, wxh
__device__ __align__(16) float g_Wd[VPAD*Hh];      // rounded + zero-padded dec_W
__device__ unsigned g_count = 0;
__device__ volatile unsigned g_epoch = 0;

// ---------------- helpers ----------------
__device__ __forceinline__ unsigned f2tf32(float x){
  unsigned u;
  asm("cvt.rna.tf32.f32 %0, %1;" : "=r"(u) : "f"(x));
  return u;
}
__device__ __forceinline__ float rndtf(float x){ return __uint_as_float(f2tf32(x)); }

__device__ __forceinline__ void mma_tf32(float* c, const unsigned* a, const unsigned* b){
  asm volatile(
    "mma.sync.aligned.m16n8k8.row.col.f32.tf32.tf32.f32 "
    "{%0,%1,%2,%3}, {%4,%5,%6,%7}, {%8,%9}, {%0,%1,%2,%3};\n"
    : "+f"(c[0]), "+f"(c[1]), "+f"(c[2]), "+f"(c[3])
    : "r"(a[0]), "r"(a[1]), "r"(a[2]), "r"(a[3]), "r"(b[0]), "r"(b[1]));
}

__device__ __forceinline__ void cpa16(void* smemp, const void* gmem){
  unsigned s = (unsigned)__cvta_generic_to_shared(smemp);
  asm volatile("cp.async.cg.shared.global [%0], [%1], 16;\n" :: "r"(s), "l"(gmem));
}
__device__ __forceinline__ void cpa_commit(){ asm volatile("cp.async.commit_group;\n"); }
template<int N> __device__ __forceinline__ void cpa_wait(){
  asm volatile("cp.async.wait_group %0;\n" :: "n"(N));
}

__device__ __forceinline__ float sigm(float x){ return 1.f/(1.f + expf(-x)); }

// grid-wide barrier; all 128 CTAs co-resident (<= #SMs)
__device__ __forceinline__ void gsync(){
  __syncthreads();
  if (threadIdx.x == 0){
    unsigned e = g_epoch;
    __threadfence();
    if (atomicAdd(&g_count, 1) == gridDim.x - 1){
      g_count = 0;
      __threadfence();
      g_epoch = e + 1;
    } else {
      while (g_epoch == e) { }
    }
    __threadfence();
  }
  __syncthreads();
}

// warp tile 64x32 (mi4 x ni4), k-block 32, smem row stride 36
__device__ __forceinline__ void compute_64x32(const float* Af, const float* Bf,
      float acc[4][4][4], int wm, int wn, int g, int tg){
  const unsigned* As = (const unsigned*)Af;
  const unsigned* Bs = (const unsigned*)Bf;
#pragma unroll
  for (int ks = 0; ks < 32; ks += 8){
    unsigned a[4][4], b[4][2];
#pragma unroll
    for (int mi = 0; mi < 4; mi++){
      int r = wm + mi*16 + g;
      a[mi][0] = As[r*36 + ks+tg];
      a[mi][1] = As[(r+8)*36 + ks+tg];
      a[mi][2] = As[r*36 + ks+tg+4];
      a[mi][3] = As[(r+8)*36 + ks+tg+4];
    }
#pragma unroll
    for (int ni = 0; ni < 4; ni++){
      int rr = wn + ni*8 + g;
      b[ni][0] = Bs[rr*36 + ks+tg];
      b[ni][1] = Bs[rr*36 + ks+tg+4];
    }
#pragma unroll
    for (int mi = 0; mi < 4; mi++)
#pragma unroll
      for (int ni = 0; ni < 4; ni++)
        mma_tf32(acc[mi][ni], a[mi], b[ni]);
  }
}

// warp tile 64x16 (mi4 x ni2) for the recurrence (CTA tile 128x64)
__device__ __forceinline__ void compute_64x16(const float* Af, const float* Bf,
      float acc[4][2][4], int wm, int wn, int g, int tg){
  const unsigned* As = (const unsigned*)Af;
  const unsigned* Bs = (const unsigned*)Bf;
#pragma unroll
  for (int ks = 0; ks < 32; ks += 8){
    unsigned a[4][4], b[2][2];
#pragma unroll
    for (int mi = 0; mi < 4; mi++){
      int r = wm + mi*16 + g;
      a[mi][0] = As[r*36 + ks+tg];
      a[mi][1] = As[(r+8)*36 + ks+tg];
      a[mi][2] = As[r*36 + ks+tg+4];
      a[mi][3] = As[(r+8)*36 + ks+tg+4];
    }
#pragma unroll
    for (int ni = 0; ni < 2; ni++){
      int rr = wn + ni*8 + g;
      b[ni][0] = Bs[rr*36 + ks+tg];
      b[ni][1] = Bs[rr*36 + ks+tg+4];
    }
#pragma unroll
    for (int mi = 0; mi < 4; mi++)
#pragma unroll
      for (int ni = 0; ni < 2; ni++)
        mma_tf32(acc[mi][ni], a[mi], b[ni]);
  }
}

// ---------------- prep: round everything to tf32 once ----------------
__global__ void __launch_bounds__(256) prep_wc(const float* __restrict__ w_hc,
                                               const float* __restrict__ edge_c){
  long i = (long)blockIdx.x*256 + threadIdx.x;
  const long N4 = (long)NBLK*Hh*Hh/4, F4 = (long)Hh*Hh/4;
  if (i >= N4) return;
  float4 v = (i < F4) ? ((const float4*)w_hc)[i] : ((const float4*)edge_c)[i-F4];
  float4 r; r.x=rndtf(v.x); r.y=rndtf(v.y); r.z=rndtf(v.z); r.w=rndtf(v.w);
  ((float4*)g_Wc)[i] = r;
}
__global__ void __launch_bounds__(256) prep_wh(const float* __restrict__ w_hh,
                                               const float* __restrict__ edge_h){
  long i = (long)blockIdx.x*256 + threadIdx.x;
  const long N4 = (long)NBLK*Hh*Hh/4, F4 = (long)Hh*Hh/4;
  if (i >= N4) return;
  float4 v = (i < F4) ? ((const float4*)w_hh)[i] : ((const float4*)edge_h)[i-F4];
  float4 r; r.x=rndtf(v.x); r.y=rndtf(v.y); r.z=rndtf(v.z); r.w=rndtf(v.w);
  ((float4*)g_Wh)[i] = r;
}
__global__ void __launch_bounds__(256) prep_we(const float* __restrict__ embW){
  long i = (long)blockIdx.x*256 + threadIdx.x;
  if (i >= (long)Vv*Ee/4) return;
  float4 v = ((const float4*)embW)[i];
  float4 r; r.x=rndtf(v.x); r.y=rndtf(v.y); r.z=rndtf(v.z); r.w=rndtf(v.w);
  ((float4*)g_We)[i] = r;
}
__global__ void __launch_bounds__(256) prep_wx(const float* __restrict__ wxcW,
                                               const float* __restrict__ wxhW){
  long i = (long)blockIdx.x*256 + threadIdx.x;
  const long F4 = (long)Hh*Ee/4;
  if (i >= 2*F4) return;
  float4 v = (i < F4) ? ((const float4*)wxcW)[i] : ((const float4*)wxhW)[i-F4];
  float4 r; r.x=rndtf(v.x); r.y=rndtf(v.y); r.z=rndtf(v.z); r.w=rndtf(v.w);
  ((float4*)g_Wx)[i] = r;
}
__global__ void __launch_bounds__(256) prep_wd(const float* __restrict__ decW){
  long i = (long)blockIdx.x*256 + threadIdx.x;
  if (i >= (long)VPAD*Hh/4) return;
  long row = (i*4) >> 10;
  float4 r = make_float4(0.f,0.f,0.f,0.f);
  if (row < Vv){
    float4 v = ((const float4*)decW)[i];
    r.x=rndtf(v.x); r.y=rndtf(v.y); r.z=rndtf(v.z); r.w=rndtf(v.w);
  }
  ((float4*)g_Wd)[i] = r;
}

// ---------------- phase 1: input projections (pipelined, pre-rounded operands) ----------------
__global__ void __launch_bounds__(256) xproj_kernel(
    const int* __restrict__ tokens,
    const float* __restrict__ wxcB, const float* __restrict__ wxhB)
{
  extern __shared__ float sm[];
  float* Ab = sm;                     // PIPE * 128*36
  float* Bbf = sm + PIPE*128*36;      // PIPE * 128*36
  __shared__ int toks[128];
  const int tid = threadIdx.x;
  const int n0 = blockIdx.x * 128;
  const int m0 = blockIdx.y * 128;
  const int mat = blockIdx.z;
  const float* W    = g_Wx + (size_t)mat*Hh*Ee;
  const float* bias = mat ? wxhB : wxcB;
  float* Cout = mat ? g_XH : g_XC;
  if (tid < 128) toks[tid] = tokens[m0 + tid];
  __syncthreads();
  const int lane = tid & 31, warp = tid >> 5;
  const int wm = (warp & 1) * 64, wn = (warp >> 1) * 32;
  const int g = lane >> 2, tg = lane & 3;

  float acc[4][4][4];
#pragma unroll
  for (int a=0;a<4;a++)
#pragma unroll
    for (int b=0;b<4;b++)
#pragma unroll
      for (int c=0;c<4;c++) acc[a][b][c]=0.f;

  auto load_tile = [&](int p, int kbi){
    int kb = kbi * 32;
#pragma unroll
    for (int i = 0; i < 4; i++){
      int idx = tid + i*256, row = idx>>3, c4 = (idx&7)*4;
      cpa16(&Ab[p*4608 + row*36 + c4], g_We + (size_t)toks[row]*Ee + kb + c4);
      cpa16(&Bbf[p*4608 + row*36 + c4], W + (size_t)(n0+row)*Ee + kb + c4);
    }
  };

#pragma unroll
  for (int p = 0; p < PIPE-1; p++){ load_tile(p, p); cpa_commit(); }
  for (int it = 0; it < 32; it++){
    cpa_wait<PIPE-2>();
    __syncthreads();
    int nx = it + PIPE - 1;
    if (nx < 32) load_tile(nx % PIPE, nx);
    cpa_commit();
    compute_64x32(Ab + (it%PIPE)*4608, Bbf + (it%PIPE)*4608, acc, wm, wn, g, tg);
  }

#pragma unroll
  for (int mi=0; mi<4; mi++){
    int r = m0 + wm + mi*16 + g;
#pragma unroll
    for (int ni=0; ni<4; ni++){
      int c = n0 + wn + ni*8 + 2*tg;
      float b0 = bias[c], b1 = bias[c+1];
      size_t o = (size_t)r*Hh + c;
      Cout[o]        = acc[mi][ni][0] + b0;
      Cout[o+1]      = acc[mi][ni][1] + b1;
      Cout[o+8*Hh]   = acc[mi][ni][2] + b0;
      Cout[o+8*Hh+1] = acc[mi][ni][3] + b1;
    }
  }
}

// ---------------- phase 2: persistent recurrence ----------------
// 128 CTAs: kc(4) x nt(16) x mat(2). CTA tile 128(M) x 64(N) x 256(K).
__global__ void __launch_bounds__(256) rnn_kernel(float* __restrict__ outp)
{
  extern __shared__ float sm[];
  float* Ab = sm;                   // PIPE * 128*36
  float* Bbf = sm + PIPE*128*36;    // PIPE * 64*36
  __shared__ float red[9];
  const int tid = threadIdx.x;
  const int bid = blockIdx.x;
  const int lane = tid & 31, warp = tid >> 5;
  const int wm = (warp & 1) * 64, wn = (warp >> 1) * 16;
  const int g = lane >> 2, tg = lane & 3;
  const int kc  = bid & 3;
  const int nt  = (bid >> 2) & 15;
  const int mat = bid >> 6;
  const int n0 = nt * 64;
  const int k0 = kc * 256;
  const int f  = bid * 256 + tid;      // float4 index over 128x1024

  // h0 = 0
  for (int i = f; i < Bb*Hh/4; i += GRID_R*256){
    ((float4*)g_H)[i]   = make_float4(0.f,0.f,0.f,0.f);
    ((float4*)g_Htf)[i] = make_float4(0.f,0.f,0.f,0.f);
  }
  gsync();

  for (int t = 0; t < Tt; t++){
    for (int s = 0; s < NBLK; s++){
      const float* W = (mat ? g_Wh : g_Wc) + (size_t)s*Hh*Hh;

      float acc[4][2][4];
#pragma unroll
      for (int a=0;a<4;a++)
#pragma unroll
        for (int b2=0;b2<2;b2++)
#pragma unroll
          for (int c=0;c<4;c++) acc[a][b2][c]=0.f;

      auto load_tile = [&](int p, int kbi){
        int kb = kbi * 32;
#pragma unroll
        for (int i = 0; i < 4; i++){
          int idx = tid + i*256, row = idx>>3, c4 = (idx&7)*4;
          cpa16(&Ab[p*4608 + row*36 + c4], g_Htf + (size_t)row*Hh + k0 + kb + c4);
        }
#pragma unroll
        for (int i = 0; i < 2; i++){
          int idx = tid + i*256, row = idx>>3, c4 = (idx&7)*4;
          cpa16(&Bbf[p*2304 + row*36 + c4], W + (size_t)(n0+row)*Hh + k0 + kb + c4);
        }
      };

#pragma unroll
      for (int p = 0; p < PIPE-1; p++){ load_tile(p, p); cpa_commit(); }
      for (int it = 0; it < 8; it++){
        cpa_wait<PIPE-2>();
        __syncthreads();
        int nx = it + PIPE - 1;
        if (nx < 8) load_tile(nx % PIPE, nx);
        cpa_commit();
        compute_64x16(Ab + (it%PIPE)*4608, Bbf + (it%PIPE)*2304, acc, wm, wn, g, tg);
      }

      // split-K partial
      float* Pd = (mat ? g_Ph : g_Pc) + ((size_t)kc << 17);
#pragma unroll
      for (int mi=0; mi<4; mi++){
        int r = wm + mi*16 + g;
#pragma unroll
        for (int ni=0; ni<2; ni++){
          int c = n0 + wn + ni*8 + 2*tg;
          Pd[(size_t)r*Hh + c]       = acc[mi][ni][0];
          Pd[(size_t)r*Hh + c+1]     = acc[mi][ni][1];
          Pd[(size_t)(r+8)*Hh + c]   = acc[mi][ni][2];
          Pd[(size_t)(r+8)*Hh + c+1] = acc[mi][ni][3];
        }
      }
      gsync();

      // fused reduce + gate + activation + blend (one float4 per thread)
      {
        float4 sc = make_float4(0.f,0.f,0.f,0.f);
        float4 sh = make_float4(0.f,0.f,0.f,0.f);
#pragma unroll
        for (int k = 0; k < 4; k++){
          float4 a  = ((const float4*)(g_Pc + ((size_t)k<<17)))[f];
          sc.x += a.x; sc.y += a.y; sc.z += a.z; sc.w += a.w;
          float4 b2 = ((const float4*)(g_Ph + ((size_t)k<<17)))[f];
          sh.x += b2.x; sh.y += b2.y; sh.z += b2.z; sh.w += b2.w;
        }
        if (s == 0){
          float4 a  = ((const float4*)(g_XC + ((size_t)t<<17)))[f];
          sc.x += a.x; sc.y += a.y; sc.z += a.z; sc.w += a.w;
          float4 b2 = ((const float4*)(g_XH + ((size_t)t<<17)))[f];
          sh.x += b2.x; sh.y += b2.y; sh.z += b2.z; sh.w += b2.w;
        }
        float4 h = ((const float4*)g_H)[f];
        const bool use_tanh = (s == 0) || (s & 1);
        float gx = sigm(sc.x), gy = sigm(sc.y), gz = sigm(sc.z), gw = sigm(sc.w);
        float ax = use_tanh ? tanhf(sh.x) : fmaxf(sh.x, 0.f);
        float ay = use_tanh ? tanhf(sh.y) : fmaxf(sh.y, 0.f);
        float az = use_tanh ? tanhf(sh.z) : fmaxf(sh.z, 0.f);
        float aw = use_tanh ? tanhf(sh.w) : fmaxf(sh.w, 0.f);
        float4 hn;
        hn.x = gx*ax + (1.f-gx)*h.x;
        hn.y = gy*ay + (1.f-gy)*h.y;
        hn.z = gz*az + (1.f-gz)*h.z;
        hn.w = gw*aw + (1.f-gw)*h.w;
        ((float4*)g_H)[f] = hn;
        float4 hr; hr.x=rndtf(hn.x); hr.y=rndtf(hn.y); hr.z=rndtf(hn.z); hr.w=rndtf(hn.w);
        ((float4*)g_Htf)[f] = hr;
        if (s == NBLK-1)
          ((float4*)(g_OUT + ((size_t)t<<17)))[f] = hr;   // pre-clip, tf32-rounded
      }
      gsync();
    }

    // per-row hidden-norm clip (CTA b owns row b)
    {
      float* hr  = g_H   + (size_t)bid * Hh;
      float* hrt = g_Htf + (size_t)bid * Hh;
      float ss = 0.f;
      for (int i = tid; i < Hh; i += 256){ float v = hr[i]; ss += v*v; }
#pragma unroll
      for (int off = 16; off > 0; off >>= 1) ss += __shfl_xor_sync(0xffffffffu, ss, off);
      if (lane == 0) red[warp] = ss;
      __syncthreads();
      if (tid == 0){
        float tot = 0.f;
        for (int w2 = 0; w2 < 8; w2++) tot += red[w2];
        float nrm = sqrtf(tot);
        red[8] = (nrm > 25.f) ? (25.f / nrm) : 1.f;
      }
      __syncthreads();
      float scale = red[8];
      if (scale != 1.f){
        for (int i = tid; i < Hh; i += 256){
          float v = hr[i] * scale;
          hr[i]  = v;
          hrt[i] = rndtf(v);
        }
      }
    }
    gsync();
  }

  // hT appended after decoded
  for (int i = f; i < Bb*Hh; i += GRID_R*256)
    outp[(size_t)Tt*Bb*Vv + i] = g_H[i];
}

// ---------------- phase 3: decoder GEMM ----------------
__global__ void __launch_bounds__(256) dec_kernel(
  const float* __restrict__ decB, float* __restrict__ outp)
{
  extern __shared__ float sm[];
  float* Ab = sm;
  float* Bbf = sm + PIPE*128*36;
  const int tid = threadIdx.x;
  const int n0 = blockIdx.x * 128;
  const int m0 = blockIdx.y * 128;
  const int lane = tid & 31, warp = tid >> 5;
  const int wm = (warp & 1) * 64, wn = (warp >> 1) * 32;
  const int g = lane >> 2, tg = lane & 3;
  float acc[4][4][4];
#pragma unroll
  for (int a=0;a<4;a++)
#pragma unroll
    for (int b=0;b<4;b++)
#pragma unroll
      for (int c=0;c<4;c++) acc[a][b][c]=0.f;

  auto load_tile = [&](int p, int kbi){
    int kb = kbi * 32;
#pragma unroll
    for (int i = 0; i < 4; i++){
      int idx = tid + i*256, row = idx>>3, c4 = (idx&7)*4;
      cpa16(&Ab[p*4608 + row*36 + c4], g_OUT + (size_t)(m0+row)*Hh + kb + c4);
      cpa16(&Bbf[p*4608 + row*36 + c4], g_Wd + (size_t)(n0+row)*Hh + kb + c4);
    }
  };

#pragma unroll
  for (int p = 0; p < PIPE-1; p++){ load_tile(p, p); cpa_commit(); }
  for (int it = 0; it < 32; it++){
    cpa_wait<PIPE-2>();
    __syncthreads();
    int nx = it + PIPE - 1;
    if (nx < 32) load_tile(nx % PIPE, nx);
    cpa_commit();
    compute_64x32(Ab + (it%PIPE)*4608, Bbf + (it%PIPE)*4608, acc, wm, wn, g, tg);
  }

#pragma unroll
  for (int mi=0;mi<4;mi++){
    int r = m0 + wm + mi*16 + g;
#pragma unroll
    for (int ni=0;ni<4;ni++){
      int c = n0 + wn + ni*8 + 2*tg;
      if (c < Vv){
        float b0 = decB[c], b1 = decB[c+1];
        size_t o  = (size_t)r*Vv + c;
        size_t o2 = o + (size_t)8*Vv;
        outp[o]    = acc[mi][ni][0] + b0;
        outp[o+1]  = acc[mi][ni][1] + b1;
        outp[o2]   = acc[mi][ni][2] + b0;
        outp[o2+1] = acc[mi][ni][3] + b1;
      }
    }
  }
}

// ---------------- launch ----------------
extern "C" void kernel_launch(void* const* d_in, const int* in_sizes, int n_in,
                              void* d_out, int out_size){
  const int*   tokens = (const int*)  d_in[0];
  const float* embW   = (const float*)d_in[1];
  const float* wxcW   = (const float*)d_in[2];
  const float* wxcB   = (const float*)d_in[3];
  const float* wxhW   = (const float*)d_in[4];
  const float* wxhB   = (const float*)d_in[5];
  const float* w_hc   = (const float*)d_in[6];
  const float* w_hh   = (const float*)d_in[7];
  const float* edge_h = (const float*)d_in[8];
  const float* edge_c = (const float*)d_in[9];
  const float* decW   = (const float*)d_in[10];
  const float* decB   = (const float*)d_in[11];
  float* outp = (float*)d_out;
  (void)in_sizes; (void)n_in; (void)out_size;

  const int RNN_SMEM  = PIPE * (128*36 + 64*36) * 4;   // 82944
  const int GEMM_SMEM = PIPE * (128*36 + 128*36) * 4;  // 110592
  cudaFuncSetAttribute(xproj_kernel, cudaFuncAttributeMaxDynamicSharedMemorySize, GEMM_SMEM);
  cudaFuncSetAttribute(rnn_kernel,   cudaFuncAttributeMaxDynamicSharedMemorySize, RNN_SMEM);
  cudaFuncSetAttribute(dec_kernel,   cudaFuncAttributeMaxDynamicSharedMemorySize, GEMM_SMEM);

  prep_wc<<<NBLK*Hh*Hh/4/256, 256>>>(w_hc, edge_c);
  prep_wh<<<NBLK*Hh*Hh/4/256, 256>>>(w_hh, edge_h);
  prep_we<<<Vv*Ee/4/256, 256>>>(embW);
  prep_wx<<<2*Hh*Ee/4/256, 256>>>(wxcW, wxhW);
  prep_wd<<<VPAD*Hh/4/256, 256>>>(decW);

  xproj_kernel<<<dim3(8, 64, 2), 256, GEMM_SMEM>>>(tokens, wxcB, wxhB);
  rnn_kernel<<<GRID_R, 256, RNN_SMEM>>>(outp);
  dec_kernel<<<dim3(VPAD/128, 64), 256, GEMM_SMEM>>>(decB, outp);
}